// round 13
// baseline (speedup 1.0000x reference)
#include <cuda_runtime.h>
#include <cuda_fp16.h>
#include <math.h>
#include <stdint.h>

#define NB 16
#define NC 256
#define NT 4096
#define TT 64

// smem: fp16 tiles, transposed [t][c], row stride 264 u16 (256 + 8 pad)
#define XS_OFF 0            // 72 rows * 264 * 2B = 38016
#define ZS_OFF 38016        // 64 rows * 264 * 2B = 33792
#define SMEM_BYTES 71808
#define ROWU16 264
#define ROWU32 132

// Prepacked fp16 weights, exact mma.sync A-fragment per-lane order.
// uint4 index = ((slot*16 + kc)*16 + mtile)*32 + lane
// slot: 0 wf_tap0, 1 wf_tap1, 2 wg_tap0, 3 wg_tap1, 4 w_res, 5 w_skip
__device__ uint4 g_wA4[6 * 16 * 16 * 32];

__device__ __forceinline__ uint32_t pack_f16(float v0, float v1) {
    __half h0 = __float2half(v0);
    __half h1 = __float2half(v1);
    uint16_t u0 = *reinterpret_cast<uint16_t*>(&h0);
    uint16_t u1 = *reinterpret_cast<uint16_t*>(&h1);
    return (uint32_t)u0 | ((uint32_t)u1 << 16);
}

__global__ void prep_wA_k(const float* __restrict__ wf, const float* __restrict__ wg,
                          const float* __restrict__ wr, const float* __restrict__ wk) {
    int idx = blockIdx.x * 256 + threadIdx.x;   // u32 index, 196608 total
    int reg  = idx & 3;
    int lane = (idx >> 2) & 31;
    int mtg  = (idx >> 7) & 15;
    int kc   = (idx >> 11) & 15;
    int slot = idx >> 15;
    int gq = lane >> 2, tq = lane & 3;
    int m  = mtg * 16 + gq + (reg & 1) * 8;
    int k0 = kc * 16 + 2 * tq + ((reg >> 1) & 1) * 8;
    float v0, v1;
    if      (slot == 0) { v0 = wf[m * 512 + k0 * 2];     v1 = wf[m * 512 + (k0 + 1) * 2]; }
    else if (slot == 1) { v0 = wf[m * 512 + k0 * 2 + 1]; v1 = wf[m * 512 + (k0 + 1) * 2 + 1]; }
    else if (slot == 2) { v0 = wg[m * 512 + k0 * 2];     v1 = wg[m * 512 + (k0 + 1) * 2]; }
    else if (slot == 3) { v0 = wg[m * 512 + k0 * 2 + 1]; v1 = wg[m * 512 + (k0 + 1) * 2 + 1]; }
    else if (slot == 4) { v0 = wr[m * 256 + k0];         v1 = wr[m * 256 + k0 + 1]; }
    else                { v0 = wk[m * 256 + k0];         v1 = wk[m * 256 + k0 + 1]; }
    reinterpret_cast<uint32_t*>(g_wA4)[idx] = pack_f16(v0, v1);
}

// f16-accumulate MMA starting from zero C; result rounds K=16 dot once to f16.
__device__ __forceinline__ void mma_f16a(uint32_t& c0, uint32_t& c1,
                                         const uint4& a, uint32_t b0, uint32_t b1) {
    asm volatile(
        "mma.sync.aligned.m16n8k16.row.col.f16.f16.f16.f16 "
        "{%0,%1}, {%2,%3,%4,%5}, {%6,%7}, {%8,%8};\n"
        : "=r"(c0), "=r"(c1)
        : "r"(a.x), "r"(a.y), "r"(a.z), "r"(a.w), "r"(b0), "r"(b1), "r"(0u));
}

// Promote f16x2 pair into fp32 masters (cvt on alu pipe, FADD on fma pipe).
__device__ __forceinline__ void promote(float* d, uint32_t c0, uint32_t c1) {
    float2 f0 = __half22float2(*reinterpret_cast<__half2*>(&c0));
    float2 f1 = __half22float2(*reinterpret_cast<__half2*>(&c1));
    d[0] = __fadd_rn(d[0], f0.x);
    d[1] = __fadd_rn(d[1], f0.y);
    d[2] = __fadd_rn(d[2], f1.x);
    d[3] = __fadd_rn(d[3], f1.y);
}

__device__ __forceinline__ float fast_tanh(float v) {
    float y;
    asm("tanh.approx.f32 %0, %1;" : "=f"(y) : "f"(v));
    return y;
}
__device__ __forceinline__ float fast_sigmoid(float v) {
    return __fdividef(1.0f, 1.0f + __expf(-v));
}

__global__ __launch_bounds__(512, 1)
void wavenet_mma_k(const float* __restrict__ x,
                   const float* __restrict__ b_f, const float* __restrict__ b_g,
                   const float* __restrict__ b_r, const float* __restrict__ b_k,
                   float* __restrict__ out_res, float* __restrict__ out_skip) {
    extern __shared__ char sm[];
    __half* xs = (__half*)(sm + XS_OFF);
    __half* zs = (__half*)(sm + ZS_OFF);

    const int tid  = threadIdx.x;
    const int warp = tid >> 5, lane = tid & 31;   // 16 warps, warp == mtile
    const int g = lane >> 2, t = lane & 3;
    const int bT = blockIdx.x * TT;
    const int bB = blockIdx.y;

    const float* xb = x + (size_t)bB * NC * NT;

    // ---- Phase A: load x tile, fp16, transposed [t][c]; rows t'=0..71 = bT-8+t' ----
    for (int it = 0; it < 9; it++) {
        int idx = it * 512 + tid;
        int row = idx / 18;           // channel
        int c   = idx - row * 18;     // float4 index along time
        int gt  = bT - 8 + c * 4;
        float4 v = make_float4(0.f, 0.f, 0.f, 0.f);
        if (gt >= 0) v = *(const float4*)(xb + row * NT + gt);
#pragma unroll
        for (int e = 0; e < 4; e++) {
            int tp = c * 4 + e;
            xs[tp * ROWU16 + row] = __float2half((&v.x)[e]);
        }
    }
    __syncthreads();

    float accP[8][4], accQ[8][4];
#pragma unroll
    for (int j = 0; j < 8; j++)
#pragma unroll
        for (int e = 0; e < 4; e++) { accP[j][e] = 0.f; accQ[j][e] = 0.f; }

    const uint4* wA4 = g_wA4;
    const uint32_t* xh = (const uint32_t*)xs + g * ROWU32 + t;

    // ---- Phase B: dilated convs (filter + gate), K=256, 2 taps ----
    for (int kc = 0; kc < 16; kc++) {
        uint32_t bh[9][2];
#pragma unroll
        for (int rg = 0; rg < 9; rg++) {
            int off = rg * (8 * ROWU32) + kc * 8;
            bh[rg][0] = xh[off]; bh[rg][1] = xh[off + 4];
        }
#pragma unroll
        for (int mg = 0; mg < 4; mg++) {       // 0:wf0 1:wf1 2:wg0 3:wg1
            uint4 a = wA4[((mg * 16 + kc) * 16 + warp) * 32 + lane];
            int ro = mg & 1;                   // tap1 reads x[t], rowgroup +1
#pragma unroll
            for (int nt = 0; nt < 8; nt++) {
                float* d = (mg < 2) ? accP[nt] : accQ[nt];
                uint32_t c0, c1;
                mma_f16a(c0, c1, a, bh[nt + ro][0], bh[nt + ro][1]);
                promote(d, c0, c1);
            }
        }
    }

    // ---- Gated activation -> z (fp16, transposed [t][o]) ----
    {
        int m0 = warp * 16 + g;
        int m1 = m0 + 8;
        float bf0 = b_f[m0], bf1 = b_f[m1];
        float bg0 = b_g[m0], bg1 = b_g[m1];
#pragma unroll
        for (int nt = 0; nt < 8; nt++) {
            int n0 = nt * 8 + 2 * t;
            float z00 = fast_tanh(accP[nt][0] + bf0) * fast_sigmoid(accQ[nt][0] + bg0);
            float z01 = fast_tanh(accP[nt][1] + bf0) * fast_sigmoid(accQ[nt][1] + bg0);
            float z10 = fast_tanh(accP[nt][2] + bf1) * fast_sigmoid(accQ[nt][2] + bg1);
            float z11 = fast_tanh(accP[nt][3] + bf1) * fast_sigmoid(accQ[nt][3] + bg1);
            zs[n0 * ROWU16 + m0]       = __float2half(z00);
            zs[(n0 + 1) * ROWU16 + m0] = __float2half(z01);
            zs[n0 * ROWU16 + m1]       = __float2half(z10);
            zs[(n0 + 1) * ROWU16 + m1] = __float2half(z11);
        }
    }
    __syncthreads();

#pragma unroll
    for (int j = 0; j < 8; j++)
#pragma unroll
        for (int e = 0; e < 4; e++) { accP[j][e] = 0.f; accQ[j][e] = 0.f; }

    const uint32_t* zh = (const uint32_t*)zs + g * ROWU32 + t;

    // ---- Phase C: both 1x1 convs over z, K=256 ----
    for (int kc = 0; kc < 16; kc++) {
        uint32_t bh[8][2];
#pragma unroll
        for (int rg = 0; rg < 8; rg++) {
            int off = rg * (8 * ROWU32) + kc * 8;
            bh[rg][0] = zh[off]; bh[rg][1] = zh[off + 4];
        }
#pragma unroll
        for (int mg = 0; mg < 2; mg++) {       // 0: w_res -> accP, 1: w_skip -> accQ
            uint4 a = wA4[(((4 + mg) * 16 + kc) * 16 + warp) * 32 + lane];
#pragma unroll
            for (int nt = 0; nt < 8; nt++) {
                float* d = (mg == 0) ? accP[nt] : accQ[nt];
                uint32_t c0, c1;
                mma_f16a(c0, c1, a, bh[nt][0], bh[nt][1]);
                promote(d, c0, c1);
            }
        }
    }

    // ---- Epilogue: res = x + P + b_r ; skip = Q + b_k ----
    {
        int m0 = warp * 16 + g;
        int m1 = m0 + 8;
        float br0 = b_r[m0], br1 = b_r[m1];
        float bk0 = b_k[m0], bk1 = b_k[m1];
        float* rp0 = out_res  + ((size_t)bB * NC + m0) * NT + bT;
        float* rp1 = out_res  + ((size_t)bB * NC + m1) * NT + bT;
        float* sp0 = out_skip + ((size_t)bB * NC + m0) * NT + bT;
        float* sp1 = out_skip + ((size_t)bB * NC + m1) * NT + bT;
        const float* xr0 = xb + (size_t)m0 * NT + bT;
        const float* xr1 = xb + (size_t)m1 * NT + bT;
#pragma unroll
        for (int nt = 0; nt < 8; nt++) {
            int n0 = nt * 8 + 2 * t;
            float2 xv0 = *(const float2*)(xr0 + n0);
            float2 xv1 = *(const float2*)(xr1 + n0);
            float2 rv0 = make_float2(xv0.x + accP[nt][0] + br0,
                                     xv0.y + accP[nt][1] + br0);
            float2 rv1 = make_float2(xv1.x + accP[nt][2] + br1,
                                     xv1.y + accP[nt][3] + br1);
            float2 sv0 = make_float2(accQ[nt][0] + bk0, accQ[nt][1] + bk0);
            float2 sv1 = make_float2(accQ[nt][2] + bk1, accQ[nt][3] + bk1);
            *(float2*)(rp0 + n0) = rv0;
            *(float2*)(rp1 + n0) = rv1;
            *(float2*)(sp0 + n0) = sv0;
            *(float2*)(sp1 + n0) = sv1;
        }
    }
}

extern "C" void kernel_launch(void* const* d_in, const int* in_sizes, int n_in,
                              void* d_out, int out_size) {
    const float* x  = (const float*)d_in[0];
    const float* wf = (const float*)d_in[1];
    const float* bf = (const float*)d_in[2];
    const float* wg = (const float*)d_in[3];
    const float* bg = (const float*)d_in[4];
    const float* wr = (const float*)d_in[5];
    const float* br = (const float*)d_in[6];
    const float* wk = (const float*)d_in[7];
    const float* bk = (const float*)d_in[8];
    float* out = (float*)d_out;

    cudaFuncSetAttribute(wavenet_mma_k,
                         cudaFuncAttributeMaxDynamicSharedMemorySize, SMEM_BYTES);

    prep_wA_k<<<768, 256>>>(wf, wg, wr, wk);
    wavenet_mma_k<<<dim3(NT / TT, NB), 512, SMEM_BYTES>>>(
        x, bf, bg, br, bk, out, out + (size_t)NB * NC * NT);
}

// round 15
// speedup vs baseline: 1.2534x; 1.2534x over previous
#include <cuda_runtime.h>
#include <cuda_fp16.h>
#include <math.h>
#include <stdint.h>

#define NB 16
#define NC 256
#define NT 4096
#define TT 64

// smem: fp16 tiles, transposed [t][c], row stride 264 u16 (256 + 8 pad)
#define XS_OFF 0            // 72 rows * 264 * 2B = 38016
#define ZS_OFF 38016        // 64 rows * 264 * 2B = 33792
#define SMEM_BYTES 71808
#define ROWU16 264
#define ROWU32 132
#define RGSTRIDE (8 * ROWU32)   // u32 stride per 8-timestep rowgroup = 1056

// Prepacked fp16 weights, exact mma.sync A-fragment per-lane order.
// uint4 index = ((slot*16 + kc)*16 + mtile)*32 + lane
// slot: 0 wf_tap0, 1 wf_tap1, 2 wg_tap0, 3 wg_tap1, 4 w_res, 5 w_skip
__device__ uint4 g_wA4[6 * 16 * 16 * 32];

__device__ __forceinline__ uint32_t pack_f16(float v0, float v1) {
    __half h0 = __float2half(v0);
    __half h1 = __float2half(v1);
    uint16_t u0 = *reinterpret_cast<uint16_t*>(&h0);
    uint16_t u1 = *reinterpret_cast<uint16_t*>(&h1);
    return (uint32_t)u0 | ((uint32_t)u1 << 16);
}

__global__ void prep_wA_k(const float* __restrict__ wf, const float* __restrict__ wg,
                          const float* __restrict__ wr, const float* __restrict__ wk) {
    int idx = blockIdx.x * 256 + threadIdx.x;   // u32 index, 196608 total
    int reg  = idx & 3;
    int lane = (idx >> 2) & 31;
    int mtg  = (idx >> 7) & 15;
    int kc   = (idx >> 11) & 15;
    int slot = idx >> 15;
    int gq = lane >> 2, tq = lane & 3;
    int m  = mtg * 16 + gq + (reg & 1) * 8;
    int k0 = kc * 16 + 2 * tq + ((reg >> 1) & 1) * 8;
    float v0, v1;
    if      (slot == 0) { v0 = wf[m * 512 + k0 * 2];     v1 = wf[m * 512 + (k0 + 1) * 2]; }
    else if (slot == 1) { v0 = wf[m * 512 + k0 * 2 + 1]; v1 = wf[m * 512 + (k0 + 1) * 2 + 1]; }
    else if (slot == 2) { v0 = wg[m * 512 + k0 * 2];     v1 = wg[m * 512 + (k0 + 1) * 2]; }
    else if (slot == 3) { v0 = wg[m * 512 + k0 * 2 + 1]; v1 = wg[m * 512 + (k0 + 1) * 2 + 1]; }
    else if (slot == 4) { v0 = wr[m * 256 + k0];         v1 = wr[m * 256 + k0 + 1]; }
    else                { v0 = wk[m * 256 + k0];         v1 = wk[m * 256 + k0 + 1]; }
    reinterpret_cast<uint32_t*>(g_wA4)[idx] = pack_f16(v0, v1);
}

__device__ __forceinline__ void mma_f16(float* d, const uint4& a, uint32_t b0, uint32_t b1) {
    asm volatile(
        "mma.sync.aligned.m16n8k16.row.col.f32.f16.f16.f32 "
        "{%0,%1,%2,%3}, {%4,%5,%6,%7}, {%8,%9}, {%0,%1,%2,%3};\n"
        : "+f"(d[0]), "+f"(d[1]), "+f"(d[2]), "+f"(d[3])
        : "r"(a.x), "r"(a.y), "r"(a.z), "r"(a.w), "r"(b0), "r"(b1));
}

__device__ __forceinline__ float fast_tanh(float v) {
    float y;
    asm("tanh.approx.f32 %0, %1;" : "=f"(y) : "f"(v));
    return y;
}
__device__ __forceinline__ float fast_sigmoid(float v) {
    return __fdividef(1.0f, 1.0f + __expf(-v));
}

__global__ __launch_bounds__(512, 1)
void wavenet_mma_k(const float* __restrict__ x,
                   const float* __restrict__ b_f, const float* __restrict__ b_g,
                   const float* __restrict__ b_r, const float* __restrict__ b_k,
                   float* __restrict__ out_res, float* __restrict__ out_skip) {
    extern __shared__ char sm[];
    __half* xs = (__half*)(sm + XS_OFF);
    __half* zs = (__half*)(sm + ZS_OFF);

    const int tid  = threadIdx.x;
    const int warp = tid >> 5, lane = tid & 31;   // 16 warps, warp == mtile
    const int g = lane >> 2, t = lane & 3;
    const int bT = blockIdx.x * TT;
    const int bB = blockIdx.y;

    const float* xb = x + (size_t)bB * NC * NT;

    // ---- Phase A: load x tile, fp16, transposed [t][c]; rows t'=0..71 = bT-8+t' ----
    for (int it = 0; it < 9; it++) {
        int idx = it * 512 + tid;
        int row = idx / 18;           // channel
        int c   = idx - row * 18;     // float4 index along time
        int gt  = bT - 8 + c * 4;
        float4 v = make_float4(0.f, 0.f, 0.f, 0.f);
        if (gt >= 0) v = *(const float4*)(xb + row * NT + gt);
#pragma unroll
        for (int e = 0; e < 4; e++) {
            int tp = c * 4 + e;
            xs[tp * ROWU16 + row] = __float2half((&v.x)[e]);
        }
    }
    __syncthreads();

    float accP[8][4], accQ[8][4];
#pragma unroll
    for (int j = 0; j < 8; j++)
#pragma unroll
        for (int e = 0; e < 4; e++) { accP[j][e] = 0.f; accQ[j][e] = 0.f; }

    // per-warp weight pointer: element ((slot*16+kc)*16+warp)*32+lane
    const uint4* wp = g_wA4 + warp * 32 + lane;
    const uint32_t* xh = (const uint32_t*)xs + g * ROWU32 + t;

    // ---- Phase B: dilated convs (filter + gate), K=256, 2 taps ----
    // slot*8192 + kc*512 element stride in uint4 units
    {
        uint4 a0, a1, a2, a3, n0, n1, n2, n3;
        n0 = wp[0 * 8192];
        n1 = wp[1 * 8192];
        n2 = wp[2 * 8192];
        n3 = wp[3 * 8192];
        for (int kc = 0; kc < 16; kc++) {
            a0 = n0; a1 = n1; a2 = n2; a3 = n3;
            if (kc < 15) {
                int o = (kc + 1) * 512;
                n0 = wp[0 * 8192 + o];
                n1 = wp[1 * 8192 + o];
                n2 = wp[2 * 8192 + o];
                n3 = wp[3 * 8192 + o];
            }
            const uint32_t* xk = xh + kc * 8;
            uint32_t bc0 = xk[0], bc1 = xk[4];          // rowgroup 0 (tap0 for nt=0)
#pragma unroll
            for (int nt = 0; nt < 8; nt++) {
                uint32_t bn0 = xk[(nt + 1) * RGSTRIDE];
                uint32_t bn1 = xk[(nt + 1) * RGSTRIDE + 4];
                mma_f16(accP[nt], a0, bc0, bc1);        // wf tap0
                mma_f16(accQ[nt], a2, bc0, bc1);        // wg tap0
                mma_f16(accP[nt], a1, bn0, bn1);        // wf tap1
                mma_f16(accQ[nt], a3, bn0, bn1);        // wg tap1
                bc0 = bn0; bc1 = bn1;
            }
        }
    }

    // ---- Gated activation -> z (fp16, transposed [t][o]) ----
    {
        int m0 = warp * 16 + g;
        int m1 = m0 + 8;
        float bf0 = b_f[m0], bf1 = b_f[m1];
        float bg0 = b_g[m0], bg1 = b_g[m1];
#pragma unroll
        for (int nt = 0; nt < 8; nt++) {
            int n0 = nt * 8 + 2 * t;
            float z00 = fast_tanh(accP[nt][0] + bf0) * fast_sigmoid(accQ[nt][0] + bg0);
            float z01 = fast_tanh(accP[nt][1] + bf0) * fast_sigmoid(accQ[nt][1] + bg0);
            float z10 = fast_tanh(accP[nt][2] + bf1) * fast_sigmoid(accQ[nt][2] + bg1);
            float z11 = fast_tanh(accP[nt][3] + bf1) * fast_sigmoid(accQ[nt][3] + bg1);
            zs[n0 * ROWU16 + m0]       = __float2half(z00);
            zs[(n0 + 1) * ROWU16 + m0] = __float2half(z01);
            zs[n0 * ROWU16 + m1]       = __float2half(z10);
            zs[(n0 + 1) * ROWU16 + m1] = __float2half(z11);
        }
    }
    __syncthreads();

#pragma unroll
    for (int j = 0; j < 8; j++)
#pragma unroll
        for (int e = 0; e < 4; e++) { accP[j][e] = 0.f; accQ[j][e] = 0.f; }

    const uint32_t* zh = (const uint32_t*)zs + g * ROWU32 + t;

    // ---- Phase C: both 1x1 convs over z, K=256 ----
    {
        uint4 a0, a1, n0, n1;
        n0 = wp[4 * 8192];
        n1 = wp[5 * 8192];
        for (int kc = 0; kc < 16; kc++) {
            a0 = n0; a1 = n1;
            if (kc < 15) {
                int o = (kc + 1) * 512;
                n0 = wp[4 * 8192 + o];
                n1 = wp[5 * 8192 + o];
            }
            const uint32_t* zk = zh + kc * 8;
#pragma unroll
            for (int nt = 0; nt < 8; nt++) {
                uint32_t b0 = zk[nt * RGSTRIDE];
                uint32_t b1 = zk[nt * RGSTRIDE + 4];
                mma_f16(accP[nt], a0, b0, b1);          // w_res
                mma_f16(accQ[nt], a1, b0, b1);          // w_skip
            }
        }
    }

    // ---- Epilogue: res = x + P + b_r ; skip = Q + b_k ----
    {
        int m0 = warp * 16 + g;
        int m1 = m0 + 8;
        float br0 = b_r[m0], br1 = b_r[m1];
        float bk0 = b_k[m0], bk1 = b_k[m1];
        float* rp0 = out_res  + ((size_t)bB * NC + m0) * NT + bT;
        float* rp1 = out_res  + ((size_t)bB * NC + m1) * NT + bT;
        float* sp0 = out_skip + ((size_t)bB * NC + m0) * NT + bT;
        float* sp1 = out_skip + ((size_t)bB * NC + m1) * NT + bT;
        const float* xr0 = xb + (size_t)m0 * NT + bT;
        const float* xr1 = xb + (size_t)m1 * NT + bT;
#pragma unroll
        for (int nt = 0; nt < 8; nt++) {
            int n0 = nt * 8 + 2 * t;
            float2 xv0 = *(const float2*)(xr0 + n0);
            float2 xv1 = *(const float2*)(xr1 + n0);
            float2 rv0 = make_float2(xv0.x + accP[nt][0] + br0,
                                     xv0.y + accP[nt][1] + br0);
            float2 rv1 = make_float2(xv1.x + accP[nt][2] + br1,
                                     xv1.y + accP[nt][3] + br1);
            float2 sv0 = make_float2(accQ[nt][0] + bk0, accQ[nt][1] + bk0);
            float2 sv1 = make_float2(accQ[nt][2] + bk1, accQ[nt][3] + bk1);
            *(float2*)(rp0 + n0) = rv0;
            *(float2*)(rp1 + n0) = rv1;
            *(float2*)(sp0 + n0) = sv0;
            *(float2*)(sp1 + n0) = sv1;
        }
    }
}

extern "C" void kernel_launch(void* const* d_in, const int* in_sizes, int n_in,
                              void* d_out, int out_size) {
    const float* x  = (const float*)d_in[0];
    const float* wf = (const float*)d_in[1];
    const float* bf = (const float*)d_in[2];
    const float* wg = (const float*)d_in[3];
    const float* bg = (const float*)d_in[4];
    const float* wr = (const float*)d_in[5];
    const float* br = (const float*)d_in[6];
    const float* wk = (const float*)d_in[7];
    const float* bk = (const float*)d_in[8];
    float* out = (float*)d_out;

    cudaFuncSetAttribute(wavenet_mma_k,
                         cudaFuncAttributeMaxDynamicSharedMemorySize, SMEM_BYTES);

    prep_wA_k<<<768, 256>>>(wf, wg, wr, wk);
    wavenet_mma_k<<<dim3(NT / TT, NB), 512, SMEM_BYTES>>>(
        x, bf, bg, br, bk, out, out + (size_t)NB * NC * NT);
}